// round 17
// baseline (speedup 1.0000x reference)
#include <cuda_runtime.h>
#include <cuda_fp16.h>
#include <cstdint>
#include <cstddef>

#define LSEQ 4096
#define LH   2048
#define NBH  128
#define CSCALE 65536.0f
#define CINV  (1.0f / 65536.0f)

// ------------------------------------------------------------- gmem scratch
__device__ __half g_Fu[64 * LH], g_Fv[64 * LH];   // fwd basis even/odd-f rows
__device__ __half g_Gte[LH * 64], g_Gto[LH * 64]; // inv basis even/odd parity
__device__ float  g_X[NBH * 64 * 128];            // [bh][e][f2]
__device__ __half g_Ce[NBH * 64 * 64], g_Co[NBH * 64 * 64];   // C * 2^16

// ------------------------------------------------------------- helpers
__device__ __forceinline__ uint32_t smem_u32(const void* p) {
    uint32_t a;
    asm("{ .reg .u64 t; cvta.to.shared.u64 t, %1; cvt.u32.u64 %0, t; }" : "=r"(a) : "l"(p));
    return a;
}
__device__ __forceinline__ void ldsm4(uint32_t* r, uint32_t addr) {
    asm volatile("ldmatrix.sync.aligned.m8n8.x4.shared.b16 {%0,%1,%2,%3}, [%4];"
                 : "=r"(r[0]), "=r"(r[1]), "=r"(r[2]), "=r"(r[3]) : "r"(addr));
}
__device__ __forceinline__ void ldsm4t(uint32_t* r, uint32_t addr) {
    asm volatile("ldmatrix.sync.aligned.m8n8.x4.trans.shared.b16 {%0,%1,%2,%3}, [%4];"
                 : "=r"(r[0]), "=r"(r[1]), "=r"(r[2]), "=r"(r[3]) : "r"(addr));
}
__device__ __forceinline__ void mma16816(float* d, const uint32_t* a, const uint32_t* b) {
    asm volatile("mma.sync.aligned.m16n8k16.row.col.f32.f16.f16.f32 "
                 "{%0,%1,%2,%3}, {%4,%5,%6,%7}, {%8,%9}, {%0,%1,%2,%3};"
                 : "+f"(d[0]), "+f"(d[1]), "+f"(d[2]), "+f"(d[3])
                 : "r"(a[0]), "r"(a[1]), "r"(a[2]), "r"(a[3]), "r"(b[0]), "r"(b[1]));
}
#define CP16(sa, gp) asm volatile("cp.async.cg.shared.global [%0], [%1], 16;" \
                                  :: "r"((uint32_t)(sa)), "l"(gp) : "memory")
#define CP_COMMIT()  asm volatile("cp.async.commit_group;" ::: "memory")
#define CP_WAIT0()   asm volatile("cp.async.wait_group 0;" ::: "memory")

// ---------------------------------------------------------------- basis init
__global__ void init_basis_kernel() {
    int idx = blockIdx.x * 256 + threadIdx.x;      // < 131072
    {   // Fu/Fv rows ru = 2*fe + c (c=0 cos, c=1 -sin), half domain
        int ru = idx >> 11, l = idx & 2047;
        int fe = ru >> 1, c = ru & 1;
        float s, cs;
        sincospif((float)((l * (2 * fe)) & 4095) / 2048.0f, &s, &cs);
        g_Fu[ru * LH + l] = __float2half(c ? -s : cs);
        sincospif((float)((l * (2 * fe + 1)) & 4095) / 2048.0f, &s, &cs);
        g_Fv[ru * LH + l] = __float2half(c ? -s : cs);
    }
    {   // Gte/Gto: [l][kk=2*fe+c], c=0 cos, c=1 +sin
        int l = idx >> 6, kk = idx & 63;
        int fe = kk >> 1, c = kk & 1;
        float s, cs;
        sincospif((float)((l * (2 * fe)) & 4095) / 2048.0f, &s, &cs);
        g_Gte[l * 64 + kk] = __float2half(c ? s : cs);
        sincospif((float)((l * (2 * fe + 1)) & 4095) / 2048.0f, &s, &cs);
        g_Gto[l * 64 + kk] = __float2half(c ? s : cs);
    }
}

// ---------------------------------------------------------------- Stage 1: DFT
// CTA = (e-quarter, bh), grid 512, 4 CTA/SM (1 wave). D[128 f2, 16 e],
// K=2048 in 32 chunks of 64. 1 sync/chunk. uv rows 48B (conflict-free ldsm).
#define D_ARR  9216                  // F array: 64 rows * 144B
#define F_STG  (2 * D_ARR)           // Fu|Fv = 18432
#define UV_ARR 3072                  // 64 rows * 48B
#define UV_STG (2 * UV_ARR)          // 6144
#define DFT_SMEM (2 * F_STG + 2 * UV_STG)   // 49152

__global__ __launch_bounds__(256, 4) void dft_fused_kernel(const float* __restrict__ q) {
    extern __shared__ char smd[];
    const uint32_t sb = smem_u32(smd);
    const int bh = blockIdx.x & 127, eq = blockIdx.x >> 7;   // e-quarter 0..3
    const int b = bh >> 3, h = bh & 7;
    const int t = threadIdx.x, w = t >> 5, lane = t & 31;
    const int grp = w >> 2, wr = w & 3;
    const float* qb = q + ((size_t)b * LSEQ * 8 + h) * 64 + eq * 16;

    const __half* srcF[2] = { g_Fu, g_Fv };

    const int ql = t >> 2, qe4 = (t & 3) * 4;   // 64 l rows, 16 e per chunk
    float4 ra, rb;
    auto LDGQ = [&](int l0) {
        const float* p = qb + (size_t)(l0 + ql) * 512 + qe4;
        ra = *(const float4*)p;
        rb = *(const float4*)(p + (size_t)LH * 512);
    };
    auto issueF = [&](int c, uint32_t stg) {     // 64 rows x 64 k per array
        const size_t k0 = (size_t)c * 64;
        #pragma unroll
        for (int i = 0; i < 4; ++i) {
            int arr = i >> 1;
            int idx = ((i & 1) << 8) + t;
            int row = idx >> 3, kg = (idx & 7) * 8;
            CP16(stg + arr * D_ARR + (uint32_t)row * 144 + kg * 2,
                 srcF[arr] + (size_t)row * LH + k0 + kg);
        }
        CP_COMMIT();
    };
    auto convert = [&](uint32_t uvoff) {          // u at +0, v at +UV_ARR; [64 l][16e]
        uint32_t ad = uvoff + (uint32_t)ql * 48 + (t & 3) * 8;
        union { uint2 v; __half x[4]; } U, V;
        U.x[0] = __float2half(ra.x + rb.x);  V.x[0] = __float2half(ra.x - rb.x);
        U.x[1] = __float2half(ra.y + rb.y);  V.x[1] = __float2half(ra.y - rb.y);
        U.x[2] = __float2half(ra.z + rb.z);  V.x[2] = __float2half(ra.z - rb.z);
        U.x[3] = __float2half(ra.w + rb.w);  V.x[3] = __float2half(ra.w - rb.w);
        *(uint2*)(smd + ad)          = U.v;
        *(uint2*)(smd + ad + UV_ARR) = V.v;
    };

    const uint32_t aoff = (uint32_t)(wr * 16 + (lane & 15)) * 144 + (lane >> 4) * 16;
    const uint32_t boff = (uint32_t)(lane & 15) * 48 + (lane >> 4) * 16;

    float acc[2][4];
    #pragma unroll
    for (int i = 0; i < 2; ++i)
        #pragma unroll
        for (int j = 0; j < 4; ++j) acc[i][j] = 0.f;

    LDGQ(0);
    issueF(0, sb);
    for (int c = 0; c < 32; ++c) {
        const uint32_t uvoff = 2 * F_STG + (uint32_t)(c & 1) * UV_STG;
        convert(uvoff);                       // writes uv(c); MMA(c-1) uses other buf
        if (c < 31) LDGQ((c + 1) * 64);       // register prefetch
        CP_WAIT0();                           // F(c) landed
        __syncthreads();                      // all warps past MMA(c-1), uv(c) visible
        if (c < 31) issueF(c + 1, sb + (uint32_t)((c + 1) & 1) * F_STG);
        const uint32_t aF = sb + (uint32_t)(c & 1) * F_STG + grp * D_ARR + aoff;
        const uint32_t bB = sb + uvoff + grp * UV_ARR + boff;
        #pragma unroll
        for (int ks = 0; ks < 4; ++ks) {
            uint32_t ah[4], bv[4];
            ldsm4(ah, aF + ks * 32);
            ldsm4t(bv, bB + ks * 768);        // 768 = 16*48
            mma16816(acc[0], ah, bv);
            mma16816(acc[1], ah, bv + 2);
        }
    }

    const int g = lane >> 2, q4 = lane & 3;
    float* xb = g_X + (size_t)bh * 8192;
    const int r0 = wr * 16 + g, r1 = r0 + 8;
    const int f2a = 2 * r0 - (r0 & 1) + 2 * grp;
    const int f2b = 2 * r1 - (r1 & 1) + 2 * grp;
    #pragma unroll
    for (int jj = 0; jj < 2; ++jj) {
        int e0 = eq * 16 + jj * 8 + q4 * 2;
        xb[e0 * 128 + f2a]       = acc[jj][0];
        xb[(e0 + 1) * 128 + f2a] = acc[jj][1];
        xb[e0 * 128 + f2b]       = acc[jj][2];
        xb[(e0 + 1) * 128 + f2b] = acc[jj][3];
    }
}

// ---------------------------------------------------------------- Stage 2: mix
// grid 256: (h, og: 8 o, bq: 4 b). cp.async double-buffered 8-e chunks,
// 1 sync per chunk. Stage = Ws_r 16K | Ws_i 16K | Xs 16K = 48KB; 2 stages.
#define M_STG  49152
#define MIX_SMEM (2 * M_STG)     // 98304
__global__ __launch_bounds__(256, 2) void mix_kernel(const float* __restrict__ wr,
                                                     const float* __restrict__ wi) {
    extern __shared__ char sm[];
    const uint32_t sb = smem_u32(sm);
    const int h = blockIdx.x & 7, og = (blockIdx.x >> 3) & 7, bq = blockIdx.x >> 6;
    const int t = threadIdx.x;
    const int f2 = t & 31, ol = t >> 5;

    auto issue = [&](int ch, uint32_t stg) {     // chunk ch covers e = ch*8..ch*8+7
        const int e0 = ch * 8;
        #pragma unroll
        for (int i = 0; i < 4; ++i) {
            int idx = (i << 8) + t;
            int row = idx >> 4, m4 = (idx & 15) * 4;
            int e = row >> 3, o = row & 7;
            size_t g = (((size_t)h * 64 + e0 + e) * 64 + og * 8 + o) * 64 + m4;
            CP16(stg + (uint32_t)row * 256 + m4 * 4, wr + g);
            CP16(stg + 16384 + (uint32_t)row * 256 + m4 * 4, wi + g);
        }
        #pragma unroll
        for (int i = 0; i < 4; ++i) {
            int idx = (i << 8) + t;
            int row = idx >> 5, f4 = (idx & 31) * 4;
            int b = row >> 3, e = row & 7;
            int bh = (bq * 4 + b) * 8 + h;
            CP16(stg + 32768 + (uint32_t)row * 512 + f4 * 4,
                 g_X + (size_t)bh * 8192 + (e0 + e) * 128 + f4);
        }
        CP_COMMIT();
    };

    float acc[4][4];
    #pragma unroll
    for (int i = 0; i < 4; ++i)
        #pragma unroll
        for (int j = 0; j < 4; ++j) acc[i][j] = 0.f;

    issue(0, sb);
    for (int ch = 0; ch < 8; ++ch) {
        const uint32_t stg = sb + (uint32_t)(ch & 1) * M_STG;
        CP_WAIT0();
        __syncthreads();
        if (ch < 7) issue(ch + 1, sb + (uint32_t)((ch + 1) & 1) * M_STG);
        const float* Ws_r = (const float*)(sm + (stg - sb));
        const float* Ws_i = (const float*)(sm + (stg - sb) + 16384);
        const float* Xs   = (const float*)(sm + (stg - sb) + 32768);
        #pragma unroll
        for (int e = 0; e < 8; ++e) {
            float2 w_r = *(const float2*)&Ws_r[(e * 8 + ol) * 64 + 2 * f2];
            float2 w_i = *(const float2*)&Ws_i[(e * 8 + ol) * 64 + 2 * f2];
            #pragma unroll
            for (int b = 0; b < 4; ++b) {
                float4 x = *(const float4*)&Xs[(b * 8 + e) * 128 + 4 * f2];
                acc[b][0] += x.x * w_r.x - x.y * w_i.x;
                acc[b][1] += x.x * w_i.x + x.y * w_r.x;
                acc[b][2] += x.z * w_r.y - x.w * w_i.y;
                acc[b][3] += x.z * w_i.y + x.w * w_r.y;
            }
        }
    }
    const float a0 = ((f2 == 0) ? (1.0f / 4096.0f) : (2.0f / 4096.0f)) * CSCALE;
    const float a1 = (2.0f / 4096.0f) * CSCALE;
    #pragma unroll
    for (int b = 0; b < 4; ++b) {
        size_t row = (size_t)((bq * 4 + b) * 8 + h) * 64 + og * 8 + ol;
        union { uint32_t u; __half x[2]; } p;
        p.x[0] = __float2half(a0 * acc[b][0]);
        p.x[1] = __float2half(-a0 * acc[b][1]);
        *(uint32_t*)&g_Ce[row * 64 + 2 * f2] = p.u;
        p.x[0] = __float2half(a1 * acc[b][2]);
        p.x[1] = __float2half(-a1 * acc[b][3]);
        *(uint32_t*)&g_Co[row * 64 + 2 * f2] = p.u;
    }
}

// ---------------------------------------------------------------- Stage 3: iDFT
// CTA = (bh, lq), grid 512, 4 CTA/SM (592 slots -> 1 wave). 1 sync/chunk.
#define IJ_ARR 9216                  // 64 rows * 144B
#define IA_SZ  (2 * IJ_ARR)          // Ce|Co = 18432
#define IG_SZ  (2 * IJ_ARR)          // Gte|Gto per stage = 18432
#define IDFT_SMEM (IA_SZ + 2 * IG_SZ)   // 55296

__global__ __launch_bounds__(256, 4) void idft_mma_kernel(float* __restrict__ out) {
    extern __shared__ char smi[];
    const uint32_t sb = smem_u32(smi);
    const int bh = blockIdx.x & 127, lq = blockIdx.x >> 7;   // lq 0..3
    const int t = threadIdx.x, w = t >> 5, lane = t & 31;
    const int w4 = w & 3, wh = w >> 2;        // row group / l-half
    const size_t pC = (size_t)bh * 64 * 64;

    const __half* srcA[2] = { g_Ce + pC, g_Co + pC };
    const __half* srcG[2] = { g_Gte, g_Gto };

    auto issueG = [&](int lc, uint32_t stg) {     // 64 l rows x 64 k, 2 arrays
        const size_t lG = (size_t)lc * 64 * 64;
        #pragma unroll
        for (int i = 0; i < 4; ++i) {
            int arr = i >> 1;
            int idx = ((i & 1) << 8) + t;
            int row = idx >> 3, kg = (idx & 7) * 8;
            CP16(stg + arr * IJ_ARR + (uint32_t)row * 144 + kg * 2,
                 srcG[arr] + lG + (size_t)row * 64 + kg);
        }
    };

    // prologue: A (2 arrays) + G(lq*8), one group
    #pragma unroll
    for (int i = 0; i < 4; ++i) {
        int arr = i >> 1;
        int idx = ((i & 1) << 8) + t;
        int row = idx >> 3, kg = (idx & 7) * 8;
        CP16(sb + arr * IJ_ARR + (uint32_t)row * 144 + kg * 2,
             srcA[arr] + (size_t)row * 64 + kg);
    }
    issueG(lq * 8, sb + IA_SZ);
    CP_COMMIT();

    const uint32_t aoff = (uint32_t)(w4 * 16 + (lane & 15)) * 144 + (lane >> 4) * 16;
    uint32_t boff[2];
    #pragma unroll
    for (int jl = 0; jl < 2; ++jl)
        boff[jl] = (uint32_t)(wh * 32 + jl * 16 + (lane >> 4) * 8 + (lane & 7)) * 144
                 + ((lane >> 3) & 1) * 16;
    const int g = lane >> 2, q4 = lane & 3;

    for (int cc = 0; cc < 8; ++cc) {
        const int lc = lq * 8 + cc;
        CP_WAIT0();
        __syncthreads();          // chunk cc data visible; all warps past chunk cc-1
        if (cc < 7) {
            issueG(lc + 1, sb + IA_SZ + (uint32_t)((cc + 1) & 1) * IG_SZ);
            CP_COMMIT();
        }
        const uint32_t gst = sb + IA_SZ + (uint32_t)(cc & 1) * IG_SZ;

        float accE[4][4], accO[4][4];
        #pragma unroll
        for (int i = 0; i < 4; ++i)
            #pragma unroll
            for (int j = 0; j < 4; ++j) { accE[i][j] = 0.f; accO[i][j] = 0.f; }

        #pragma unroll
        for (int p = 0; p < 2; ++p) {
            float (*acc)[4] = p ? accO : accE;
            const uint32_t aC = sb + (uint32_t)p * IJ_ARR + aoff;
            const uint32_t gb = gst + (uint32_t)p * IJ_ARR;
            #pragma unroll
            for (int ks = 0; ks < 4; ++ks) {
                uint32_t ac[4];
                ldsm4(ac, aC + ks * 32);
                #pragma unroll
                for (int jl = 0; jl < 2; ++jl) {
                    uint32_t bh_[4];
                    ldsm4(bh_, gb + boff[jl] + ks * 32);
                    mma16816(acc[2 * jl],     ac, bh_);
                    mma16816(acc[2 * jl + 1], ac, bh_ + 2);
                }
            }
        }

        // register combine + direct stores (4-lane groups form 32B segments)
        const int r0 = w4 * 16 + g;
        float* o0 = out + ((size_t)bh * 64 + r0) * LSEQ + lc * 64 + wh * 32 + q4 * 2;
        float* o1 = o0 + (size_t)8 * LSEQ;
        #pragma unroll
        for (int jj = 0; jj < 4; ++jj) {
            float e0 = accE[jj][0], e1 = accE[jj][1], o0v = accO[jj][0], o1v = accO[jj][1];
            float e2 = accE[jj][2], e3 = accE[jj][3], o2v = accO[jj][2], o3v = accO[jj][3];
            *(float2*)(o0 + jj * 8)      = make_float2((e0 + o0v) * CINV, (e1 + o1v) * CINV);
            *(float2*)(o0 + LH + jj * 8) = make_float2((e0 - o0v) * CINV, (e1 - o1v) * CINV);
            *(float2*)(o1 + jj * 8)      = make_float2((e2 + o2v) * CINV, (e3 + o3v) * CINV);
            *(float2*)(o1 + LH + jj * 8) = make_float2((e2 - o2v) * CINV, (e3 - o3v) * CINV);
        }
    }
}

// ---------------------------------------------------------------------------
extern "C" void kernel_launch(void* const* d_in, const int* in_sizes, int n_in,
                              void* d_out, int out_size) {
    const float* q = (const float*)d_in[0];
    const float* wr = nullptr;
    const float* wi = nullptr;
    for (int i = 0; i < n_in; ++i) {
        if (in_sizes[i] == 8 * 64 * 64 * 64) {
            if (!wr) wr = (const float*)d_in[i];
            else if (!wi) wi = (const float*)d_in[i];
        }
    }
    float* out = (float*)d_out;

    cudaFuncSetAttribute(dft_fused_kernel, cudaFuncAttributeMaxDynamicSharedMemorySize, DFT_SMEM);
    cudaFuncSetAttribute(mix_kernel,       cudaFuncAttributeMaxDynamicSharedMemorySize, MIX_SMEM);
    cudaFuncSetAttribute(idft_mma_kernel,  cudaFuncAttributeMaxDynamicSharedMemorySize, IDFT_SMEM);

    init_basis_kernel<<<512, 256>>>();
    dft_fused_kernel<<<512, 256, DFT_SMEM>>>(q);
    mix_kernel<<<256, 256, MIX_SMEM>>>(wr, wi);
    idft_mma_kernel<<<512, 256, IDFT_SMEM>>>(out);
}